// round 6
// baseline (speedup 1.0000x reference)
#include <cuda_runtime.h>
#include <stdint.h>

// Problem constants (fixed shapes)
#define Bb 4
#define Cc 3
#define Hh 32
#define Ww 32
#define Dd 32
#define KK 32
#define KHALF 16
#define OHh 30
#define OWw 30
#define ODd 30

// tile: [c(3)][kh(3)][dw(6)][d(32)] = 1728 floats; 3 copies shifted by 0/1/2 floats
#define TILE_N 1728
#define SM_N   (3*TILE_N)

__device__ float4 g_coef[KK * 31];   // (c0, ca, cb, cab) per (k, node)
__device__ int4   g_off4[KK * 8];    // per (k, leafpair j): a(2j), b(2j), a(2j+1), b(2j+1)

// ---------------- prep kernel ----------------
__global__ void prep_kernel(const int* __restrict__ kc,
                            const float* __restrict__ w0, const float* __restrict__ w1,
                            const float* __restrict__ w2, const float* __restrict__ w3,
                            const float* __restrict__ w4) {
    int i = blockIdx.x * blockDim.x + threadIdx.x;
    if (i < KK * 31) {
        int k = i / 31, n = i % 31;
        const float* w; int node;
        if (n < 16)      { w = w0; node = n; }
        else if (n < 24) { w = w1; node = n - 16; }
        else if (n < 28) { w = w2; node = n - 24; }
        else if (n < 30) { w = w3; node = n - 28; }
        else             { w = w4; node = 0; }
        const float* p = w + (node * KK + k) * 16;
        float m = p[0];
#pragma unroll
        for (int g = 1; g < 16; ++g) m = fmaxf(m, p[g]);
        float e[16]; float s = 0.f;
#pragma unroll
        for (int g = 0; g < 16; ++g) { e[g] = expf(p[g] - m); s += e[g]; }
        float inv = 1.f / s;
        float l0 = 0.f, l1 = 0.f, l2 = 0.f, l3 = 0.f;
#pragma unroll
        for (int g = 0; g < 16; ++g) {
            float pg = e[g] * inv;
            if (g & 1) l0 += pg;
            if (g & 2) l1 += pg;
            if (g & 4) l2 += pg;
            if (g & 8) l3 += pg;
        }
        // val = c0 + ca*a + cb*b + cab*a*b
        g_coef[k * 31 + n] = make_float4(l0, l2 - l0, l1 - l0, l3 - l2 - l1 + l0);
    }
    if (i < KK * 8) {
        int k = i / 8, j = i % 8;
        int o[4];
#pragma unroll
        for (int e2 = 0; e2 < 2; ++e2) {       // leaf 2j + e2
            int s = 2 * j + e2;
#pragma unroll
            for (int r = 0; r < 2; ++r) {
                const int* c4 = kc + (((r * KK + k) * 16 + s) << 2);
                int hh = c4[0], ww = c4[1], dd = c4[2], cc = c4[3];  // (h,w,d,c) in [0,3)
                int B0 = ((cc * 3 + hh) * 6 + ww) * 32;
                o[2 * e2 + r] = dd * TILE_N + B0;   // copy #dd: copy_dd[i] = tile[i+dd]
            }
        }
        g_off4[i] = make_int4(o[0], o[1], o[2], o[3]);
    }
}

// ---------------- packed f32x2 helpers ----------------
typedef unsigned long long u64;

__device__ __forceinline__ u64 fma2(u64 a, u64 b, u64 c) {
    u64 d;
    asm("fma.rn.f32x2 %0, %1, %2, %3;" : "=l"(d) : "l"(a), "l"(b), "l"(c));
    return d;
}
__device__ __forceinline__ u64 pack2(float x) {
    u64 d;
    asm("mov.b64 %0, {%1, %1};" : "=l"(d) : "f"(x));
    return d;
}

struct V2 { u64 lo, hi; };   // 4 fp32 values (4 consecutive od)

__device__ __forceinline__ V2 lut4(V2 a, V2 b, float4 c) {
    u64 c0 = pack2(c.x), ca = pack2(c.y), cb = pack2(c.z), cab = pack2(c.w);
    V2 r;
    r.lo = fma2(a.lo, fma2(cab, b.lo, ca), fma2(cb, b.lo, c0));
    r.hi = fma2(a.hi, fma2(cab, b.hi, ca), fma2(cb, b.hi, c0));
    return r;
}
__device__ __forceinline__ V2 leaf(const float* __restrict__ sml, int ao, int bo, float4 c) {
    ulonglong2 a = *reinterpret_cast<const ulonglong2*>(sml + ao);
    ulonglong2 b = *reinterpret_cast<const ulonglong2*>(sml + bo);
    V2 va = {a.x, a.y}, vb = {b.x, b.y};
    return lut4(va, vb, c);
}

// level bases in coef array: leaves 0..15, L1 16..23, L2 24..27, L3 28..29, L4 30
template <int L> struct LvlBase { static constexpr int v = 32 - (32 >> L); };

template <int L, int J>
__device__ __forceinline__ V2 eval_node(const float* __restrict__ sml,
                                        const int4* __restrict__ of4,
                                        const float4* __restrict__ cf) {
    if constexpr (L == 1) {
        int4 o = of4[J];
        V2 a = leaf(sml, o.x, o.y, cf[2 * J]);
        V2 b = leaf(sml, o.z, o.w, cf[2 * J + 1]);
        return lut4(a, b, cf[16 + J]);
    } else {
        V2 a = eval_node<L - 1, 2 * J>(sml, of4, cf);
        V2 b = eval_node<L - 1, 2 * J + 1>(sml, of4, cf);
        return lut4(a, b, cf[LvlBase<L>::v + J]);
    }
}

// ---------------- main kernel ----------------
// grid: (8 ow-groups, 30 oh, 8 = b(4) x khalf(2)); block 256 (8 warps)
// lane: row = l>>3 (4 ow rows), q = l&7 (od quad; q==7 -> od 28,29 valid only)
// warp w handles k_local = {w, w+8} within its k-half.
__global__ void __launch_bounds__(256, 6) logic_kernel(const float* __restrict__ x,
                                                       float* __restrict__ out) {
    __shared__ float  sm[SM_N];
    __shared__ float4 scoef[KHALF * 31];
    __shared__ int4   soff4[KHALF * 8];

    const int tid = threadIdx.x;
    const int bg  = blockIdx.x;             // ow group (4 rows)
    const int oh  = blockIdx.y;
    const int bz  = blockIdx.z >> 1;        // batch
    const int kh  = blockIdx.z & 1;         // k half
    const int ow0 = bg * 4;

    const float* xb = x + bz * (Cc * Hh * Ww * Dd);

    // Stage tile + 2 shifted copies. tile[i], i = ((c*3+kh)*6+dw)*32 + d
    for (int i = tid; i < TILE_N; i += 256) {
        int rr  = i / 192;            // c*3+r, 0..8
        int rem = i - rr * 192;
        int dw  = rem >> 5;
        int d   = rem & 31;
        int c   = rr / 3;
        int r   = rr - c * 3;
        int w_in = ow0 + dw; if (w_in > 31) w_in = 31;   // clamp (masked rows only)
        float v = xb[((c * Hh + (oh + r)) * Ww + w_in) * Dd + d];
        sm[i] = v;
        if (i >= 1) sm[TILE_N - 1 + i] = v;       // copy1[i-1] = tile[i]
        if (i >= 2) sm[2 * TILE_N - 2 + i] = v;   // copy2[i-2] = tile[i]
    }
    if (tid == 0) { sm[2 * TILE_N - 1] = 0.f; sm[3 * TILE_N - 2] = 0.f; sm[3 * TILE_N - 1] = 0.f; }
    for (int i = tid; i < KHALF * 31; i += 256) scoef[i] = g_coef[kh * (KHALF * 31) + i];
    for (int i = tid; i < KHALF * 8; i += 256)  soff4[i] = g_off4[kh * (KHALF * 8) + i];
    __syncthreads();

    const int w   = tid >> 5;
    const int l   = tid & 31;
    const int row = l >> 3;           // 0..3
    const int q   = l & 7;            // od quad
    const float* sml = sm + row * 32 + 4 * q;
    const int ow  = ow0 + row;
    const bool rv = (ow < OWw);

#pragma unroll 1
    for (int kk = 0; kk < 2; ++kk) {
        const int k_local = (kk << 3) + w;
        const float4* cf  = scoef + k_local * 31;
        const int4*   of4 = soff4 + k_local * 8;

        V2 r = eval_node<4, 0>(sml, of4, cf);

        if (rv) {
            int k = kh * KHALF + k_local;
            int base = (((bz * KK + k) * OHh + oh) * OWw + ow) * ODd + 4 * q;
            *reinterpret_cast<float2*>(out + base) = *reinterpret_cast<float2*>(&r.lo);
            if (q < 7)
                *reinterpret_cast<float2*>(out + base + 2) = *reinterpret_cast<float2*>(&r.hi);
        }
    }
}

// ---------------- launch ----------------
extern "C" void kernel_launch(void* const* d_in, const int* in_sizes, int n_in,
                              void* d_out, int out_size) {
    const float* x  = (const float*)d_in[0];
    const int*   kc = (const int*)d_in[1];
    const float* w0 = (const float*)d_in[2];
    const float* w1 = (const float*)d_in[3];
    const float* w2 = (const float*)d_in[4];
    const float* w3 = (const float*)d_in[5];
    const float* w4 = (const float*)d_in[6];
    float* out = (float*)d_out;

    // Hint: give L1 carveout fully to shared memory (not a stream op; graph-safe).
    static bool attr_done = false;
    if (!attr_done) {
        cudaFuncSetAttribute(logic_kernel, cudaFuncAttributePreferredSharedMemoryCarveout,
                             cudaSharedmemCarveoutMaxShared);
        attr_done = true;
    }

    prep_kernel<<<8, 128>>>(kc, w0, w1, w2, w3, w4);
    dim3 grid((OWw + 3) / 4, OHh, Bb * 2);
    logic_kernel<<<grid, 256>>>(x, out);
}

// round 7
// speedup vs baseline: 1.0166x; 1.0166x over previous
#include <cuda_runtime.h>
#include <stdint.h>

// Problem constants (fixed shapes)
#define Bb 4
#define Cc 3
#define Hh 32
#define Ww 32
#define Dd 32
#define KK 32
#define KHALF 16
#define OHh 30
#define OWw 30
#define ODd 30

// tile: [c(3)][kh(3)][dw(6)][d(32)] = 1728 floats; 3 copies shifted by 0/1/2 floats
#define TILE_N 1728
#define SM_N   (3*TILE_N)

__device__ float4 g_coef[KK * 31];   // (c0, ca, cb, cab) per (k, node)
__device__ int4   g_off4[KK * 8];    // per (k, leafpair j): a(2j), b(2j), a(2j+1), b(2j+1)

// ---------------- prep kernel ----------------
__global__ void prep_kernel(const int* __restrict__ kc,
                            const float* __restrict__ w0, const float* __restrict__ w1,
                            const float* __restrict__ w2, const float* __restrict__ w3,
                            const float* __restrict__ w4) {
    int i = blockIdx.x * blockDim.x + threadIdx.x;
    if (i < KK * 31) {
        int k = i / 31, n = i % 31;
        const float* w; int node;
        if (n < 16)      { w = w0; node = n; }
        else if (n < 24) { w = w1; node = n - 16; }
        else if (n < 28) { w = w2; node = n - 24; }
        else if (n < 30) { w = w3; node = n - 28; }
        else             { w = w4; node = 0; }
        const float* p = w + (node * KK + k) * 16;
        float m = p[0];
#pragma unroll
        for (int g = 1; g < 16; ++g) m = fmaxf(m, p[g]);
        float e[16]; float s = 0.f;
#pragma unroll
        for (int g = 0; g < 16; ++g) { e[g] = expf(p[g] - m); s += e[g]; }
        float inv = 1.f / s;
        float l0 = 0.f, l1 = 0.f, l2 = 0.f, l3 = 0.f;
#pragma unroll
        for (int g = 0; g < 16; ++g) {
            float pg = e[g] * inv;
            if (g & 1) l0 += pg;
            if (g & 2) l1 += pg;
            if (g & 4) l2 += pg;
            if (g & 8) l3 += pg;
        }
        // val = c0 + ca*a + cb*b + cab*a*b
        g_coef[k * 31 + n] = make_float4(l0, l2 - l0, l1 - l0, l3 - l2 - l1 + l0);
    }
    if (i < KK * 8) {
        int k = i / 8, j = i % 8;
        int o[4];
#pragma unroll
        for (int e2 = 0; e2 < 2; ++e2) {       // leaf 2j + e2
            int s = 2 * j + e2;
#pragma unroll
            for (int r = 0; r < 2; ++r) {
                const int* c4 = kc + (((r * KK + k) * 16 + s) << 2);
                int hh = c4[0], ww = c4[1], dd = c4[2], cc = c4[3];  // (h,w,d,c) in [0,3)
                int B0 = ((cc * 3 + hh) * 6 + ww) * 32;
                o[2 * e2 + r] = dd * TILE_N + B0;   // copy #dd: copy_dd[i] = tile[i+dd]
            }
        }
        g_off4[i] = make_int4(o[0], o[1], o[2], o[3]);
    }
}

// ---------------- packed f32x2 helpers ----------------
typedef unsigned long long u64;

__device__ __forceinline__ u64 fma2(u64 a, u64 b, u64 c) {
    u64 d;
    asm("fma.rn.f32x2 %0, %1, %2, %3;" : "=l"(d) : "l"(a), "l"(b), "l"(c));
    return d;
}
__device__ __forceinline__ u64 pack2(float x) {
    u64 d;
    asm("mov.b64 %0, {%1, %1};" : "=l"(d) : "f"(x));
    return d;
}

struct V2 { u64 lo, hi; };   // 4 fp32 values (4 consecutive od)

__device__ __forceinline__ V2 lut4(V2 a, V2 b, float4 c) {
    u64 c0 = pack2(c.x), ca = pack2(c.y), cb = pack2(c.z), cab = pack2(c.w);
    V2 r;
    r.lo = fma2(a.lo, fma2(cab, b.lo, ca), fma2(cb, b.lo, c0));
    r.hi = fma2(a.hi, fma2(cab, b.hi, ca), fma2(cb, b.hi, c0));
    return r;
}
__device__ __forceinline__ V2 leaf(const float* __restrict__ sml, int ao, int bo, float4 c) {
    ulonglong2 a = *reinterpret_cast<const ulonglong2*>(sml + ao);
    ulonglong2 b = *reinterpret_cast<const ulonglong2*>(sml + bo);
    V2 va = {a.x, a.y}, vb = {b.x, b.y};
    return lut4(va, vb, c);
}

// level bases in coef array: leaves 0..15, L1 16..23, L2 24..27, L3 28..29, L4 30
template <int L> struct LvlBase { static constexpr int v = 32 - (32 >> L); };

template <int L, int J>
__device__ __forceinline__ V2 eval_node(const float* __restrict__ sml,
                                        const int4* __restrict__ of4,
                                        const float4* __restrict__ cf) {
    if constexpr (L == 1) {
        int4 o = of4[J];
        V2 a = leaf(sml, o.x, o.y, cf[2 * J]);
        V2 b = leaf(sml, o.z, o.w, cf[2 * J + 1]);
        return lut4(a, b, cf[16 + J]);
    } else {
        V2 a = eval_node<L - 1, 2 * J>(sml, of4, cf);
        V2 b = eval_node<L - 1, 2 * J + 1>(sml, of4, cf);
        return lut4(a, b, cf[LvlBase<L>::v + J]);
    }
}

// ---------------- main kernel ----------------
// grid: (8 ow-groups, 30 oh, 8 = b(4) x khalf(2)); block 256 (8 warps)
// lane: row = l>>3 (4 ow rows), q = l&7 (od quad; q==7 -> od 28,29 valid only)
// warp w handles k_local = {w, w+8} within its k-half.
__global__ void __launch_bounds__(256, 6) logic_kernel(const float* __restrict__ x,
                                                       float* __restrict__ out) {
    __shared__ float  sm[SM_N];
    __shared__ float4 scoef[KHALF * 31];
    __shared__ int4   soff4[KHALF * 8];

    const int tid = threadIdx.x;
    const int bg  = blockIdx.x;             // ow group (4 rows)
    const int oh  = blockIdx.y;
    const int bz  = blockIdx.z >> 1;        // batch
    const int kh  = blockIdx.z & 1;         // k half
    const int ow0 = bg * 4;

    const float* xb = x + bz * (Cc * Hh * Ww * Dd);

    // Stage tile + 2 shifted copies. tile[i], i = ((c*3+kh)*6+dw)*32 + d
    for (int i = tid; i < TILE_N; i += 256) {
        int rr  = i / 192;            // c*3+r, 0..8
        int rem = i - rr * 192;
        int dw  = rem >> 5;
        int d   = rem & 31;
        int c   = rr / 3;
        int r   = rr - c * 3;
        int w_in = ow0 + dw; if (w_in > 31) w_in = 31;   // clamp (masked rows only)
        float v = xb[((c * Hh + (oh + r)) * Ww + w_in) * Dd + d];
        sm[i] = v;
        if (i >= 1) sm[TILE_N - 1 + i] = v;       // copy1[i-1] = tile[i]
        if (i >= 2) sm[2 * TILE_N - 2 + i] = v;   // copy2[i-2] = tile[i]
    }
    if (tid == 0) { sm[2 * TILE_N - 1] = 0.f; sm[3 * TILE_N - 2] = 0.f; sm[3 * TILE_N - 1] = 0.f; }
    for (int i = tid; i < KHALF * 31; i += 256) scoef[i] = g_coef[kh * (KHALF * 31) + i];
    for (int i = tid; i < KHALF * 8; i += 256)  soff4[i] = g_off4[kh * (KHALF * 8) + i];
    __syncthreads();

    const int w   = tid >> 5;
    const int l   = tid & 31;
    const int row = l >> 3;           // 0..3
    const int q   = l & 7;            // od quad
    const float* sml = sm + row * 32 + 4 * q;
    const int ow  = ow0 + row;
    const bool rv = (ow < OWw);

#pragma unroll 1
    for (int kk = 0; kk < 2; ++kk) {
        const int k_local = (kk << 3) + w;
        const float4* cf  = scoef + k_local * 31;
        const int4*   of4 = soff4 + k_local * 8;

        V2 r = eval_node<4, 0>(sml, of4, cf);

        if (rv) {
            int k = kh * KHALF + k_local;
            int base = (((bz * KK + k) * OHh + oh) * OWw + ow) * ODd + 4 * q;
            *reinterpret_cast<float2*>(out + base) = *reinterpret_cast<float2*>(&r.lo);
            if (q < 7)
                *reinterpret_cast<float2*>(out + base + 2) = *reinterpret_cast<float2*>(&r.hi);
        }
    }
}

// ---------------- launch ----------------
extern "C" void kernel_launch(void* const* d_in, const int* in_sizes, int n_in,
                              void* d_out, int out_size) {
    const float* x  = (const float*)d_in[0];
    const int*   kc = (const int*)d_in[1];
    const float* w0 = (const float*)d_in[2];
    const float* w1 = (const float*)d_in[3];
    const float* w2 = (const float*)d_in[4];
    const float* w3 = (const float*)d_in[5];
    const float* w4 = (const float*)d_in[6];
    float* out = (float*)d_out;

    // Hint: give L1 carveout fully to shared memory (not a stream op; graph-safe).
    static bool attr_done = false;
    if (!attr_done) {
        cudaFuncSetAttribute(logic_kernel, cudaFuncAttributePreferredSharedMemoryCarveout,
                             cudaSharedmemCarveoutMaxShared);
        attr_done = true;
    }

    prep_kernel<<<8, 128>>>(kc, w0, w1, w2, w3, w4);
    dim3 grid((OWw + 3) / 4, OHh, Bb * 2);
    logic_kernel<<<grid, 256>>>(x, out);
}

// round 8
// speedup vs baseline: 1.0535x; 1.0363x over previous
#include <cuda_runtime.h>
#include <stdint.h>

// Problem constants (fixed shapes)
#define Bb 4
#define Cc 3
#define Hh 32
#define Ww 32
#define Dd 32
#define KK 32
#define KHALF 16
#define OHh 30
#define OWw 30
#define ODd 30

// tile: [c(3)][kh(3)][dw(6)][d(32)] = 1728 floats; 3 copies shifted by 0/1/2 floats
#define TILE_N 1728
#define SM_N   (3*TILE_N)

__device__ float4 g_coef[KK * 31];   // (c0, ca, cb, cab) per (k, node)
__device__ int4   g_off4[KK * 8];    // per (k, leafpair j): a(2j), b(2j), a(2j+1), b(2j+1)

// ---------------- prep kernel ----------------
__global__ void prep_kernel(const int* __restrict__ kc,
                            const float* __restrict__ w0, const float* __restrict__ w1,
                            const float* __restrict__ w2, const float* __restrict__ w3,
                            const float* __restrict__ w4) {
    int i = blockIdx.x * blockDim.x + threadIdx.x;
    if (i < KK * 31) {
        int k = i / 31, n = i % 31;
        const float* w; int node;
        if (n < 16)      { w = w0; node = n; }
        else if (n < 24) { w = w1; node = n - 16; }
        else if (n < 28) { w = w2; node = n - 24; }
        else if (n < 30) { w = w3; node = n - 28; }
        else             { w = w4; node = 0; }
        const float* p = w + (node * KK + k) * 16;
        float m = p[0];
#pragma unroll
        for (int g = 1; g < 16; ++g) m = fmaxf(m, p[g]);
        float e[16]; float s = 0.f;
#pragma unroll
        for (int g = 0; g < 16; ++g) { e[g] = expf(p[g] - m); s += e[g]; }
        float inv = 1.f / s;
        float l0 = 0.f, l1 = 0.f, l2 = 0.f, l3 = 0.f;
#pragma unroll
        for (int g = 0; g < 16; ++g) {
            float pg = e[g] * inv;
            if (g & 1) l0 += pg;
            if (g & 2) l1 += pg;
            if (g & 4) l2 += pg;
            if (g & 8) l3 += pg;
        }
        // val = c0 + ca*a + cb*b + cab*a*b
        g_coef[k * 31 + n] = make_float4(l0, l2 - l0, l1 - l0, l3 - l2 - l1 + l0);
    }
    if (i < KK * 8) {
        int k = i / 8, j = i % 8;
        int o[4];
#pragma unroll
        for (int e2 = 0; e2 < 2; ++e2) {       // leaf 2j + e2
            int s = 2 * j + e2;
#pragma unroll
            for (int r = 0; r < 2; ++r) {
                const int* c4 = kc + (((r * KK + k) * 16 + s) << 2);
                int hh = c4[0], ww = c4[1], dd = c4[2], cc = c4[3];  // (h,w,d,c) in [0,3)
                int B0 = ((cc * 3 + hh) * 6 + ww) * 32;
                o[2 * e2 + r] = dd * TILE_N + B0;   // copy #dd: copy_dd[i] = tile[i+dd]
            }
        }
        g_off4[i] = make_int4(o[0], o[1], o[2], o[3]);
    }
}

// ---------------- packed f32x2 helpers ----------------
typedef unsigned long long u64;

__device__ __forceinline__ u64 fma2(u64 a, u64 b, u64 c) {
    u64 d;
    asm("fma.rn.f32x2 %0, %1, %2, %3;" : "=l"(d) : "l"(a), "l"(b), "l"(c));
    return d;
}
__device__ __forceinline__ u64 pack2(float x) {
    u64 d;
    asm("mov.b64 %0, {%1, %1};" : "=l"(d) : "f"(x));
    return d;
}

struct V2 { u64 lo, hi; };   // 4 fp32 values (4 consecutive od)

__device__ __forceinline__ V2 lut4(V2 a, V2 b, float4 c) {
    u64 c0 = pack2(c.x), ca = pack2(c.y), cb = pack2(c.z), cab = pack2(c.w);
    V2 r;
    r.lo = fma2(a.lo, fma2(cab, b.lo, ca), fma2(cb, b.lo, c0));
    r.hi = fma2(a.hi, fma2(cab, b.hi, ca), fma2(cb, b.hi, c0));
    return r;
}
__device__ __forceinline__ V2 leaf(const float* __restrict__ sml, int ao, int bo, float4 c) {
    ulonglong2 a = *reinterpret_cast<const ulonglong2*>(sml + ao);
    ulonglong2 b = *reinterpret_cast<const ulonglong2*>(sml + bo);
    V2 va = {a.x, a.y}, vb = {b.x, b.y};
    return lut4(va, vb, c);
}

// level bases in coef array: leaves 0..15, L1 16..23, L2 24..27, L3 28..29, L4 30
template <int L> struct LvlBase { static constexpr int v = 32 - (32 >> L); };

template <int L, int J>
__device__ __forceinline__ V2 eval_node(const float* __restrict__ sml,
                                        const int4* __restrict__ of4,
                                        const float4* __restrict__ cf) {
    if constexpr (L == 1) {
        int4 o = of4[J];
        V2 a = leaf(sml, o.x, o.y, cf[2 * J]);
        V2 b = leaf(sml, o.z, o.w, cf[2 * J + 1]);
        return lut4(a, b, cf[16 + J]);
    } else {
        V2 a = eval_node<L - 1, 2 * J>(sml, of4, cf);
        V2 b = eval_node<L - 1, 2 * J + 1>(sml, of4, cf);
        return lut4(a, b, cf[LvlBase<L>::v + J]);
    }
}

// ---------------- main kernel ----------------
// grid: (8 ow-groups, 30 oh, 8 = b(4) x khalf(2)); block 256 (8 warps)
// lane: row = l>>3 (4 ow rows), q = l&7 (od quad; q==7 -> od 28,29 valid only)
// warp w handles k_local = {w, w+8} within its k-half.
__global__ void __launch_bounds__(256, 6) logic_kernel(const float* __restrict__ x,
                                                       float* __restrict__ out) {
    __shared__ float  sm[SM_N];
    __shared__ float4 scoef[KHALF * 31];
    __shared__ int4   soff4[KHALF * 8];

    const int tid = threadIdx.x;
    const int bg  = blockIdx.x;             // ow group (4 rows)
    const int oh  = blockIdx.y;
    const int bz  = blockIdx.z >> 1;        // batch
    const int kh  = blockIdx.z & 1;         // k half
    const int ow0 = bg * 4;

    const float* xb = x + bz * (Cc * Hh * Ww * Dd);

    // Stage tile + 2 shifted copies. tile[i], i = ((c*3+kh)*6+dw)*32 + d
    for (int i = tid; i < TILE_N; i += 256) {
        int rr  = i / 192;            // c*3+r, 0..8
        int rem = i - rr * 192;
        int dw  = rem >> 5;
        int d   = rem & 31;
        int c   = rr / 3;
        int r   = rr - c * 3;
        int w_in = ow0 + dw; if (w_in > 31) w_in = 31;   // clamp (masked rows only)
        float v = xb[((c * Hh + (oh + r)) * Ww + w_in) * Dd + d];
        sm[i] = v;
        if (i >= 1) sm[TILE_N - 1 + i] = v;       // copy1[i-1] = tile[i]
        if (i >= 2) sm[2 * TILE_N - 2 + i] = v;   // copy2[i-2] = tile[i]
    }
    if (tid == 0) { sm[2 * TILE_N - 1] = 0.f; sm[3 * TILE_N - 2] = 0.f; sm[3 * TILE_N - 1] = 0.f; }
    for (int i = tid; i < KHALF * 31; i += 256) scoef[i] = g_coef[kh * (KHALF * 31) + i];
    for (int i = tid; i < KHALF * 8; i += 256)  soff4[i] = g_off4[kh * (KHALF * 8) + i];
    __syncthreads();

    const int w   = tid >> 5;
    const int l   = tid & 31;
    const int row = l >> 3;           // 0..3
    const int q   = l & 7;            // od quad
    const float* sml = sm + row * 32 + 4 * q;
    const int ow  = ow0 + row;
    const bool rv = (ow < OWw);

#pragma unroll 1
    for (int kk = 0; kk < 2; ++kk) {
        const int k_local = (kk << 3) + w;
        const float4* cf  = scoef + k_local * 31;
        const int4*   of4 = soff4 + k_local * 8;

        V2 r = eval_node<4, 0>(sml, of4, cf);

        if (rv) {
            int k = kh * KHALF + k_local;
            int base = (((bz * KK + k) * OHh + oh) * OWw + ow) * ODd + 4 * q;
            *reinterpret_cast<float2*>(out + base) = *reinterpret_cast<float2*>(&r.lo);
            if (q < 7)
                *reinterpret_cast<float2*>(out + base + 2) = *reinterpret_cast<float2*>(&r.hi);
        }
    }
}

// ---------------- launch ----------------
extern "C" void kernel_launch(void* const* d_in, const int* in_sizes, int n_in,
                              void* d_out, int out_size) {
    const float* x  = (const float*)d_in[0];
    const int*   kc = (const int*)d_in[1];
    const float* w0 = (const float*)d_in[2];
    const float* w1 = (const float*)d_in[3];
    const float* w2 = (const float*)d_in[4];
    const float* w3 = (const float*)d_in[5];
    const float* w4 = (const float*)d_in[6];
    float* out = (float*)d_out;

    // Hint: give L1 carveout fully to shared memory (not a stream op; graph-safe).
    static bool attr_done = false;
    if (!attr_done) {
        cudaFuncSetAttribute(logic_kernel, cudaFuncAttributePreferredSharedMemoryCarveout,
                             cudaSharedmemCarveoutMaxShared);
        attr_done = true;
    }

    prep_kernel<<<8, 128>>>(kc, w0, w1, w2, w3, w4);
    dim3 grid((OWw + 3) / 4, OHh, Bb * 2);
    logic_kernel<<<grid, 256>>>(x, out);
}